// round 2
// baseline (speedup 1.0000x reference)
#include <cuda_runtime.h>
#include <math.h>

#define N_VARS 50000
#define HID 128
#define N_EDGES 400000
#define NP 50048            // padded to multiple of 64
#define STEPS 4
#define BN_EPS 1e-5f

// ---------------- scratch (static device memory; no allocation) ----------------
__device__ float g_hA[NP * HID];
__device__ float g_hB[NP * HID];
__device__ float g_c[NP * HID];
__device__ float g_agg[NP * HID];
__device__ float g_rec[NP * HID];
__device__ float g_degf[NP];
__device__ float g_Wp1[256 * HID];        // [k][j]      : transposed W_msg
__device__ float g_Wp2[256 * 4 * HID];    // [k][j][gate]: fused W_ih|W_hh, permuted
__device__ float g_bias[4 * HID];         // b_ih + b_hh
__device__ float g_stats[2 * HID];        // col sums / sumsq of rec
__device__ float g_bnA[HID];
__device__ float g_bnB[HID];

__device__ __forceinline__ float sigf(float x) { return 1.0f / (1.0f + expf(-x)); }

// ---------------- one-time prep: weight permutations + fused bias ----------------
__global__ void prep_kernel(const float* __restrict__ W_msg,
                            const float* __restrict__ W_ih,
                            const float* __restrict__ W_hh,
                            const float* __restrict__ b_ih,
                            const float* __restrict__ b_hh) {
    int t = blockIdx.x * blockDim.x + threadIdx.x;
    int stride = gridDim.x * blockDim.x;
    // Wp1[k*128 + j] = W_msg[j][k]   (k in [0,256), j in [0,128))
    for (int i = t; i < 256 * HID; i += stride) {
        int k = i >> 7, j = i & 127;
        g_Wp1[i] = W_msg[j * 256 + k];
    }
    // Wp2[k*512 + j*4 + g] = (k<128 ? W_ih : W_hh)[g*128 + j][k mod 128]
    for (int i = t; i < 256 * 512; i += stride) {
        int k = i >> 9, r = i & 511;
        int j = r >> 2, g = r & 3;
        int wrow = g * HID + j;
        g_Wp2[i] = (k < HID) ? W_ih[wrow * HID + k] : W_hh[wrow * HID + (k - HID)];
    }
    for (int i = t; i < 4 * HID; i += stride) g_bias[i] = b_ih[i] + b_hh[i];
}

// ---------------- degree (float counts; exact for small ints) ----------------
__global__ void deg_kernel(const int* __restrict__ ei) {
    int i = blockIdx.x * blockDim.x + threadIdx.x;
    if (i < 2 * N_EDGES) atomicAdd(&g_degf[ei[i]], 1.0f);
}

// ---------------- edge aggregation: agg[v] = sum_{(u->v)} h[u] ----------------
__global__ void agg_kernel(const int* __restrict__ ei, const float* __restrict__ hin) {
    int w = (blockIdx.x * blockDim.x + threadIdx.x) >> 5;  // one warp per undirected edge
    int lane = threadIdx.x & 31;
    if (w >= N_EDGES) return;
    int a = ei[w];
    int b = ei[N_EDGES + w];
    int c4 = lane * 4;
    float4 ha = *(const float4*)&hin[(size_t)a * HID + c4];
    float4 hb = *(const float4*)&hin[(size_t)b * HID + c4];
    float* pb = &g_agg[(size_t)b * HID + c4];
    atomicAdd(pb + 0, ha.x); atomicAdd(pb + 1, ha.y);
    atomicAdd(pb + 2, ha.z); atomicAdd(pb + 3, ha.w);
    float* pa = &g_agg[(size_t)a * HID + c4];
    atomicAdd(pa + 0, hb.x); atomicAdd(pa + 1, hb.y);
    atomicAdd(pa + 2, hb.z); atomicAdd(pa + 3, hb.w);
}

// ---------------- GEMM1: rec = ([agg | deg*h] @ Wp1) * var_reg, + col stats ----------------
__global__ void __launch_bounds__(256) rec_gemm(const float* __restrict__ hin,
                                                const float* __restrict__ var_reg) {
    __shared__ __align__(16) float Xs[64][32];
    __shared__ __align__(16) float Ws[32][128];
    const int tid = threadIdx.x;
    const int tx = tid & 31, ty = tid >> 5;
    const int rowBase = blockIdx.x * 64;
    float acc[8][4];
#pragma unroll
    for (int i = 0; i < 8; i++)
#pragma unroll
        for (int c = 0; c < 4; c++) acc[i][c] = 0.f;

    for (int k0 = 0; k0 < 256; k0 += 32) {
#pragma unroll
        for (int t = tid; t < 512; t += 256) {          // 64 rows x 8 float4
            int r = t >> 3, kq = t & 7;
            int row = rowBase + r;
            int gk = k0 + kq * 4;
            float4 v;
            if (gk < HID) {
                v = *(const float4*)&g_agg[(size_t)row * HID + gk];
            } else {
                v = *(const float4*)&hin[(size_t)row * HID + (gk - HID)];
                float d = g_degf[row];
                v.x *= d; v.y *= d; v.z *= d; v.w *= d;
            }
            *(float4*)&Xs[r][kq * 4] = v;
        }
#pragma unroll
        for (int t = tid; t < 1024; t += 256) {         // 32 kk x 32 float4
            int kk = t >> 5, jq = t & 31;
            *(float4*)&Ws[kk][jq * 4] = *(const float4*)&g_Wp1[(k0 + kk) * HID + jq * 4];
        }
        __syncthreads();
#pragma unroll
        for (int kq = 0; kq < 8; ++kq) {
            float4 w0 = *(float4*)&Ws[kq * 4 + 0][tx * 4];
            float4 w1 = *(float4*)&Ws[kq * 4 + 1][tx * 4];
            float4 w2 = *(float4*)&Ws[kq * 4 + 2][tx * 4];
            float4 w3 = *(float4*)&Ws[kq * 4 + 3][tx * 4];
#pragma unroll
            for (int i = 0; i < 8; ++i) {
                float4 x = *(float4*)&Xs[ty * 8 + i][kq * 4];
                acc[i][0] = fmaf(x.x, w0.x, fmaf(x.y, w1.x, fmaf(x.z, w2.x, fmaf(x.w, w3.x, acc[i][0]))));
                acc[i][1] = fmaf(x.x, w0.y, fmaf(x.y, w1.y, fmaf(x.z, w2.y, fmaf(x.w, w3.y, acc[i][1]))));
                acc[i][2] = fmaf(x.x, w0.z, fmaf(x.y, w1.z, fmaf(x.z, w2.z, fmaf(x.w, w3.z, acc[i][2]))));
                acc[i][3] = fmaf(x.x, w0.w, fmaf(x.y, w1.w, fmaf(x.z, w2.w, fmaf(x.w, w3.w, acc[i][3]))));
            }
        }
        __syncthreads();
    }
    float s[4] = {0, 0, 0, 0}, s2[4] = {0, 0, 0, 0};
#pragma unroll
    for (int i = 0; i < 8; i++) {
        int row = rowBase + ty * 8 + i;
        float vr = (row < N_VARS) ? var_reg[row] : 0.f;   // pad rows -> 0 (no stat pollution)
        float4 o;
        o.x = acc[i][0] * vr; o.y = acc[i][1] * vr;
        o.z = acc[i][2] * vr; o.w = acc[i][3] * vr;
        *(float4*)&g_rec[(size_t)row * HID + tx * 4] = o;
        s[0] += o.x; s[1] += o.y; s[2] += o.z; s[3] += o.w;
        s2[0] += o.x * o.x; s2[1] += o.y * o.y; s2[2] += o.z * o.z; s2[3] += o.w * o.w;
    }
#pragma unroll
    for (int c = 0; c < 4; c++) {
        atomicAdd(&g_stats[tx * 4 + c], s[c]);
        atomicAdd(&g_stats[HID + tx * 4 + c], s2[c]);
    }
}

// ---------------- BN finalize: fold gamma/beta/mean/var into per-column affine ----------------
__global__ void bn_finalize(const float* __restrict__ gamma, const float* __restrict__ beta) {
    int j = threadIdx.x;
    float mean = g_stats[j] * (1.0f / N_VARS);
    float var = g_stats[HID + j] * (1.0f / N_VARS) - mean * mean;
    float a = gamma[j] * rsqrtf(var + BN_EPS);
    g_bnA[j] = a;
    g_bnB[j] = beta[j] - mean * a;
}

// ---------------- GEMM2 + LSTM: gates = [BN(rec) | h] @ Wp2, fused pointwise ----------------
__global__ void __launch_bounds__(256) gates_gemm(const float* __restrict__ hin,
                                                  float* __restrict__ hout) {
    __shared__ __align__(16) float Xs[64][32];
    __shared__ __align__(16) float Ws[32][128];
    const int tid = threadIdx.x;
    const int tx = tid & 31, ty = tid >> 5;
    const int rowBase = blockIdx.x * 64;
    const int jBase = blockIdx.y * 32;
    float acc[8][4];
#pragma unroll
    for (int i = 0; i < 8; i++)
#pragma unroll
        for (int c = 0; c < 4; c++) acc[i][c] = 0.f;

    for (int k0 = 0; k0 < 256; k0 += 32) {
#pragma unroll
        for (int t = tid; t < 512; t += 256) {
            int r = t >> 3, kq = t & 7;
            int row = rowBase + r;
            int gk = k0 + kq * 4;
            float4 v;
            if (gk < HID) {
                v = *(const float4*)&g_rec[(size_t)row * HID + gk];
                float4 a = *(const float4*)&g_bnA[gk];
                float4 b = *(const float4*)&g_bnB[gk];
                v.x = fmaf(v.x, a.x, b.x); v.y = fmaf(v.y, a.y, b.y);
                v.z = fmaf(v.z, a.z, b.z); v.w = fmaf(v.w, a.w, b.w);
            } else {
                v = *(const float4*)&hin[(size_t)row * HID + (gk - HID)];
            }
            *(float4*)&Xs[r][kq * 4] = v;
        }
#pragma unroll
        for (int t = tid; t < 1024; t += 256) {
            int kk = t >> 5, jq = t & 31;
            *(float4*)&Ws[kk][jq * 4] =
                *(const float4*)&g_Wp2[(size_t)(k0 + kk) * 512 + jBase * 4 + jq * 4];
        }
        __syncthreads();
#pragma unroll
        for (int kq = 0; kq < 8; ++kq) {
            float4 w0 = *(float4*)&Ws[kq * 4 + 0][tx * 4];
            float4 w1 = *(float4*)&Ws[kq * 4 + 1][tx * 4];
            float4 w2 = *(float4*)&Ws[kq * 4 + 2][tx * 4];
            float4 w3 = *(float4*)&Ws[kq * 4 + 3][tx * 4];
#pragma unroll
            for (int i = 0; i < 8; ++i) {
                float4 x = *(float4*)&Xs[ty * 8 + i][kq * 4];
                acc[i][0] = fmaf(x.x, w0.x, fmaf(x.y, w1.x, fmaf(x.z, w2.x, fmaf(x.w, w3.x, acc[i][0]))));
                acc[i][1] = fmaf(x.x, w0.y, fmaf(x.y, w1.y, fmaf(x.z, w2.y, fmaf(x.w, w3.y, acc[i][1]))));
                acc[i][2] = fmaf(x.x, w0.z, fmaf(x.y, w1.z, fmaf(x.z, w2.z, fmaf(x.w, w3.z, acc[i][2]))));
                acc[i][3] = fmaf(x.x, w0.w, fmaf(x.y, w1.w, fmaf(x.z, w2.w, fmaf(x.w, w3.w, acc[i][3]))));
            }
        }
        __syncthreads();
    }
    // fused LSTM pointwise epilogue (acc[.][0..3] = i,f,g,o for column j)
    int j = jBase + tx;
    float bi = g_bias[j], bf = g_bias[HID + j], bg = g_bias[2 * HID + j], bo = g_bias[3 * HID + j];
#pragma unroll
    for (int i = 0; i < 8; i++) {
        int row = rowBase + ty * 8 + i;
        size_t idx = (size_t)row * HID + j;
        float ig = acc[i][0] + bi;
        float fg = acc[i][1] + bf;
        float gg = acc[i][2] + bg;
        float og = acc[i][3] + bo;
        float cold = g_c[idx];
        float cn = sigf(fg) * cold + sigf(ig) * tanhf(gg);
        g_c[idx] = cn;
        hout[idx] = sigf(og) * tanhf(cn);
    }
}

// ---------------- output: softmax(h @ W_out^T) ----------------
__global__ void out_kernel(const float* __restrict__ hin,
                           const float* __restrict__ W_out,
                           float* __restrict__ out) {
    int v = (blockIdx.x * blockDim.x + threadIdx.x) >> 5;
    int lane = threadIdx.x & 31;
    if (v >= N_VARS) return;
    float p0 = 0.f, p1 = 0.f, p2 = 0.f;
#pragma unroll
    for (int q = 0; q < 4; q++) {
        int col = lane + q * 32;
        float hv = hin[(size_t)v * HID + col];
        p0 = fmaf(hv, __ldg(&W_out[col]), p0);
        p1 = fmaf(hv, __ldg(&W_out[HID + col]), p1);
        p2 = fmaf(hv, __ldg(&W_out[2 * HID + col]), p2);
    }
#pragma unroll
    for (int o = 16; o > 0; o >>= 1) {
        p0 += __shfl_xor_sync(0xffffffffu, p0, o);
        p1 += __shfl_xor_sync(0xffffffffu, p1, o);
        p2 += __shfl_xor_sync(0xffffffffu, p2, o);
    }
    if (lane == 0) {
        float m = fmaxf(p0, fmaxf(p1, p2));
        float e0 = expf(p0 - m), e1 = expf(p1 - m), e2 = expf(p2 - m);
        float inv = 1.f / (e0 + e1 + e2);
        out[v * 3 + 0] = e0 * inv;
        out[v * 3 + 1] = e1 * inv;
        out[v * 3 + 2] = e2 * inv;
    }
}

// ---------------- launch ----------------
extern "C" void kernel_launch(void* const* d_in, const int* in_sizes, int n_in,
                              void* d_out, int out_size) {
    const float* h0      = (const float*)d_in[0];
    const float* var_reg = (const float*)d_in[1];
    const float* W_msg   = (const float*)d_in[2];
    const float* gamma   = (const float*)d_in[3];
    const float* beta    = (const float*)d_in[4];
    const float* W_ih    = (const float*)d_in[5];
    const float* W_hh    = (const float*)d_in[6];
    const float* b_ih    = (const float*)d_in[7];
    const float* b_hh    = (const float*)d_in[8];
    const float* W_out   = (const float*)d_in[9];
    const int*   ei      = (const int*)d_in[10];
    (void)in_sizes; (void)n_in;

    float *hA, *hB, *cbuf, *agg, *deg, *stats;
    cudaGetSymbolAddress((void**)&hA, g_hA);
    cudaGetSymbolAddress((void**)&hB, g_hB);
    cudaGetSymbolAddress((void**)&cbuf, g_c);
    cudaGetSymbolAddress((void**)&agg, g_agg);
    cudaGetSymbolAddress((void**)&deg, g_degf);
    cudaGetSymbolAddress((void**)&stats, g_stats);

    cudaStream_t s = 0;
    cudaMemcpyAsync(hA, h0, (size_t)N_VARS * HID * sizeof(float),
                    cudaMemcpyDeviceToDevice, s);
    cudaMemsetAsync(hA + (size_t)N_VARS * HID, 0,
                    (size_t)(NP - N_VARS) * HID * sizeof(float), s);
    cudaMemsetAsync(cbuf, 0, (size_t)NP * HID * sizeof(float), s);
    cudaMemsetAsync(deg, 0, (size_t)NP * sizeof(float), s);

    prep_kernel<<<512, 256, 0, s>>>(W_msg, W_ih, W_hh, b_ih, b_hh);
    deg_kernel<<<(2 * N_EDGES + 255) / 256, 256, 0, s>>>(ei);

    const float* hin = hA;
    float* hout = hB;
    for (int st = 0; st < STEPS; ++st) {
        cudaMemsetAsync(agg, 0, (size_t)NP * HID * sizeof(float), s);
        cudaMemsetAsync(stats, 0, 2 * HID * sizeof(float), s);
        agg_kernel<<<N_EDGES / 8, 256, 0, s>>>(ei, hin);
        rec_gemm<<<NP / 64, 256, 0, s>>>(hin, var_reg);
        bn_finalize<<<1, HID, 0, s>>>(gamma, beta);
        gates_gemm<<<dim3(NP / 64, 4), 256, 0, s>>>(hin, hout);
        const float* tmp = hout;
        hout = (float*)hin;
        hin = tmp;
    }
    out_kernel<<<(N_VARS * 32 + 255) / 256, 256, 0, s>>>(hin, W_out, (float*)d_out);
}

// round 4
// speedup vs baseline: 1.0835x; 1.0835x over previous
#include <cuda_runtime.h>
#include <cuda_bf16.h>
#include <math.h>
#include <stdint.h>

#define N_VARS 50000
#define HID 128
#define N_EDGES 400000
#define NP 50048            // 391 * 128
#define NBLK (NP / 128)     // 391
#define STEPS 4
#define BN_EPS 1e-5f

// ---------------- static device scratch ----------------
__device__ float g_hA[NP * HID];
__device__ float g_hB[NP * HID];
__device__ float g_c[NP * HID];
__device__ float g_agg[NP * HID];
__device__ float g_rec[NP * HID];
__device__ float g_degf[NP];
__device__ __align__(16) __nv_bfloat16 g_W1h[128 * 256];   // rec weights  [n][k]
__device__ __align__(16) __nv_bfloat16 g_W1l[128 * 256];
__device__ __align__(16) __nv_bfloat16 g_W2h[512 * 256];   // gate weights [n=4j+g][k]
__device__ __align__(16) __nv_bfloat16 g_W2l[512 * 256];
__device__ float g_bias[4 * HID];
__device__ float g_stats[2 * HID];
__device__ __align__(16) float g_bnA[HID];
__device__ __align__(16) float g_bnB[HID];

__device__ __forceinline__ float sigf(float x) { return 1.0f / (1.0f + expf(-x)); }

__device__ __forceinline__ uint32_t smem_u32(const void* p) {
    uint32_t a;
    asm("{ .reg .u64 t; cvta.to.shared.u64 t, %1; cvt.u32.u64 %0, t; }" : "=r"(a) : "l"(p));
    return a;
}
#define SWZ(o) ((o) ^ (((o) >> 3) & 0x70))

#define LDSM4(R, A) \
    asm volatile("ldmatrix.sync.aligned.m8n8.x4.shared.b16 {%0,%1,%2,%3}, [%4];" \
                 : "=r"((R)[0]), "=r"((R)[1]), "=r"((R)[2]), "=r"((R)[3]) : "r"(A))

#define MMA(C, A, B0, B1) \
    asm volatile("mma.sync.aligned.m16n8k16.row.col.f32.bf16.bf16.f32 " \
                 "{%0,%1,%2,%3},{%4,%5,%6,%7},{%8,%9},{%0,%1,%2,%3};" \
                 : "+f"((C)[0]), "+f"((C)[1]), "+f"((C)[2]), "+f"((C)[3]) \
                 : "r"((A)[0]), "r"((A)[1]), "r"((A)[2]), "r"((A)[3]), "r"(B0), "r"(B1))

union Pack8 { __nv_bfloat16 b[8]; uint4 u; };
__device__ __forceinline__ void split8(float4 a, float4 b, uint4& hi, uint4& lo) {
    float v[8] = {a.x, a.y, a.z, a.w, b.x, b.y, b.z, b.w};
    Pack8 ph, pl;
#pragma unroll
    for (int i = 0; i < 8; i++) {
        __nv_bfloat16 h = __float2bfloat16(v[i]);
        ph.b[i] = h;
        pl.b[i] = __float2bfloat16(v[i] - __bfloat162float(h));
    }
    hi = ph.u; lo = pl.u;
}

// smem tile offsets (relative to 1K-aligned base); each tile 128 rows x 64 bf16 (128B rows)
#define T_A_HI 0
#define T_A_LO 16384
#define T_B_HI 32768
#define T_B_LO 49152
#define SMEMSZ (1024 + 65536)

// ---------------- prep: bf16-split weights, fused bias ----------------
__global__ void prep_kernel(const float* __restrict__ W_msg,
                            const float* __restrict__ W_ih,
                            const float* __restrict__ W_hh,
                            const float* __restrict__ b_ih,
                            const float* __restrict__ b_hh) {
    int t = blockIdx.x * blockDim.x + threadIdx.x;
    int stride = gridDim.x * blockDim.x;
    for (int i = t; i < 128 * 256; i += stride) {      // W1[n][k] = W_msg[n][k]
        float w = W_msg[i];
        __nv_bfloat16 h = __float2bfloat16(w);
        g_W1h[i] = h;
        g_W1l[i] = __float2bfloat16(w - __bfloat162float(h));
    }
    for (int i = t; i < 512 * 256; i += stride) {      // W2[n=4j+g][k]
        int n = i >> 8, k = i & 255;
        int j = n >> 2, g = n & 3;
        int wrow = g * HID + j;
        float w = (k < HID) ? W_ih[wrow * HID + k] : W_hh[wrow * HID + (k - HID)];
        __nv_bfloat16 h = __float2bfloat16(w);
        g_W2h[i] = h;
        g_W2l[i] = __float2bfloat16(w - __bfloat162float(h));
    }
    for (int i = t; i < 4 * HID; i += stride) g_bias[i] = b_ih[i] + b_hh[i];
}

// ---------------- degree ----------------
__global__ void deg_kernel(const int* __restrict__ ei) {
    int i = blockIdx.x * blockDim.x + threadIdx.x;
    if (i < 2 * N_EDGES) atomicAdd(&g_degf[ei[i]], 1.0f);
}

// ---------------- edge aggregation ----------------
__global__ void agg_kernel(const int* __restrict__ ei, const float* __restrict__ hin) {
    int w = (blockIdx.x * blockDim.x + threadIdx.x) >> 5;
    int lane = threadIdx.x & 31;
    if (w >= N_EDGES) return;
    int a = ei[w];
    int b = ei[N_EDGES + w];
    int c4 = lane * 4;
    float4 ha = *(const float4*)&hin[(size_t)a * HID + c4];
    float4 hb = *(const float4*)&hin[(size_t)b * HID + c4];
    float* pb = &g_agg[(size_t)b * HID + c4];
    atomicAdd(pb + 0, ha.x); atomicAdd(pb + 1, ha.y);
    atomicAdd(pb + 2, ha.z); atomicAdd(pb + 3, ha.w);
    float* pa = &g_agg[(size_t)a * HID + c4];
    atomicAdd(pa + 0, hb.x); atomicAdd(pa + 1, hb.y);
    atomicAdd(pa + 2, hb.z); atomicAdd(pa + 3, hb.w);
}

// ---------------- warp-tile compute core (one K-chunk of 64) ----------------
// warp tile: 32 rows x 64 cols; acc[2 mtiles][8 ntiles][4]
__device__ __forceinline__ void chunk_compute(uint32_t sb, int warpRow, int warpCol,
                                              int lane, float acc[2][8][4]) {
#pragma unroll
    for (int ks = 0; ks < 4; ks++) {
        uint32_t aH[2][4], aL[2][4];
#pragma unroll
        for (int mt = 0; mt < 2; mt++) {
            uint32_t off = (uint32_t)((warpRow + mt * 16 + (lane & 15)) * 128
                                      + ks * 32 + ((lane >> 4) & 1) * 16);
            uint32_t sw = SWZ(off);
            LDSM4(aH[mt], sb + T_A_HI + sw);
            LDSM4(aL[mt], sb + T_A_LO + sw);
        }
#pragma unroll
        for (int np = 0; np < 4; np++) {
            uint32_t bH[4], bL[4];
            uint32_t off = (uint32_t)((warpCol + np * 16 + ((lane >> 4) & 1) * 8 + (lane & 7)) * 128
                                      + ks * 32 + ((lane >> 3) & 1) * 16);
            uint32_t sw = SWZ(off);
            LDSM4(bH, sb + T_B_HI + sw);
            LDSM4(bL, sb + T_B_LO + sw);
#pragma unroll
            for (int mt = 0; mt < 2; mt++) {
#pragma unroll
                for (int nt = 0; nt < 2; nt++) {
                    float* c = acc[mt][np * 2 + nt];
                    MMA(c, aH[mt], bH[nt * 2], bH[nt * 2 + 1]);
                    MMA(c, aH[mt], bL[nt * 2], bL[nt * 2 + 1]);
                    MMA(c, aL[mt], bH[nt * 2], bH[nt * 2 + 1]);
                }
            }
        }
    }
}

// ---------------- rec = ([agg | deg*h] @ W1^T) * var_reg ----------------
__global__ void __launch_bounds__(256, 1)
rec_mma(const float* __restrict__ hin, const float* __restrict__ var_reg) {
    extern __shared__ char smraw[];
    uint32_t sb0 = smem_u32(smraw);
    uint32_t sb = (sb0 + 1023) & ~1023u;
    char* smp = smraw + (sb - sb0);
    const int tid = threadIdx.x;
    const int wid = tid >> 5, lane = tid & 31;
    const int rowBase = blockIdx.x * 128;
    const int warpRow = (wid >> 1) * 32, warpCol = (wid & 1) * 64;

    float acc[2][8][4];
#pragma unroll
    for (int m = 0; m < 2; m++)
#pragma unroll
        for (int n = 0; n < 8; n++)
#pragma unroll
            for (int c = 0; c < 4; c++) acc[m][n][c] = 0.f;

    for (int chunk = 0; chunk < 4; chunk++) {
        const int k0 = chunk * 64;
        // A stage: fp32 -> bf16 hi/lo, swizzled
        for (int idx = tid; idx < 1024; idx += 256) {
            int row = idx >> 3, i = idx & 7;
            int gk = k0 + i * 8;
            float4 v0, v1;
            if (k0 < HID) {
                const float* src = &g_agg[(size_t)(rowBase + row) * HID + gk];
                v0 = *(const float4*)src; v1 = *(const float4*)(src + 4);
            } else {
                const float* src = &hin[(size_t)(rowBase + row) * HID + (gk - HID)];
                v0 = *(const float4*)src; v1 = *(const float4*)(src + 4);
                float d = g_degf[rowBase + row];
                v0.x *= d; v0.y *= d; v0.z *= d; v0.w *= d;
                v1.x *= d; v1.y *= d; v1.z *= d; v1.w *= d;
            }
            uint4 hi, lo; split8(v0, v1, hi, lo);
            uint32_t sw = SWZ((uint32_t)(row * 128 + i * 16));
            *(uint4*)(smp + T_A_HI + sw) = hi;
            *(uint4*)(smp + T_A_LO + sw) = lo;
        }
        // B stage: W1 rows 0..127
        for (int idx = tid; idx < 1024; idx += 256) {
            int row = idx >> 3, i = idx & 7;
            uint32_t sw = SWZ((uint32_t)(row * 128 + i * 16));
            int gi = row * 32 + (k0 >> 3) + i;
            *(uint4*)(smp + T_B_HI + sw) = ((const uint4*)g_W1h)[gi];
            *(uint4*)(smp + T_B_LO + sw) = ((const uint4*)g_W1l)[gi];
        }
        __syncthreads();
        chunk_compute(sb, warpRow, warpCol, lane, acc);
        __syncthreads();
    }

    // epilogue: scale by var_reg, direct stores
#pragma unroll
    for (int mt = 0; mt < 2; mt++) {
        int r0 = rowBase + warpRow + mt * 16 + (lane >> 2);
        int r1 = r0 + 8;
        float vr0 = (r0 < N_VARS) ? var_reg[r0] : 0.f;
        float vr1 = (r1 < N_VARS) ? var_reg[r1] : 0.f;
#pragma unroll
        for (int n8 = 0; n8 < 8; n8++) {
            int col = warpCol + n8 * 8 + 2 * (lane & 3);
            float* c = acc[mt][n8];
            float2 o0 = make_float2(c[0] * vr0, c[1] * vr0);
            float2 o1 = make_float2(c[2] * vr1, c[3] * vr1);
            *(float2*)&g_rec[(size_t)r0 * HID + col] = o0;
            *(float2*)&g_rec[(size_t)r1 * HID + col] = o1;
        }
    }
}

// ---------------- column stats of rec (pads are zero) ----------------
__global__ void stats_kernel() {
    int tid = threadIdx.x;
    int tx = tid & 31, ty = tid >> 5;
    int rowBase = blockIdx.x * 128 + ty * 16;
    float s[4] = {0, 0, 0, 0}, s2[4] = {0, 0, 0, 0};
#pragma unroll
    for (int i = 0; i < 16; i++) {
        float4 v = *(const float4*)&g_rec[(size_t)(rowBase + i) * HID + tx * 4];
        s[0] += v.x; s[1] += v.y; s[2] += v.z; s[3] += v.w;
        s2[0] += v.x * v.x; s2[1] += v.y * v.y; s2[2] += v.z * v.z; s2[3] += v.w * v.w;
    }
#pragma unroll
    for (int c = 0; c < 4; c++) {
        atomicAdd(&g_stats[tx * 4 + c], s[c]);
        atomicAdd(&g_stats[HID + tx * 4 + c], s2[c]);
    }
}

__global__ void bn_finalize(const float* __restrict__ gamma, const float* __restrict__ beta) {
    int j = threadIdx.x;
    float mean = g_stats[j] * (1.0f / N_VARS);
    float var = g_stats[HID + j] * (1.0f / N_VARS) - mean * mean;
    float a = gamma[j] * rsqrtf(var + BN_EPS);
    g_bnA[j] = a;
    g_bnB[j] = beta[j] - mean * a;
}

// ---------------- gates = [BN(rec) | h] @ W2^T + LSTM pointwise ----------------
__global__ void __launch_bounds__(256, 1)
gates_mma(const float* __restrict__ hin, float* __restrict__ hout) {
    extern __shared__ char smraw[];
    uint32_t sb0 = smem_u32(smraw);
    uint32_t sb = (sb0 + 1023) & ~1023u;
    char* smp = smraw + (sb - sb0);
    const int tid = threadIdx.x;
    const int wid = tid >> 5, lane = tid & 31;
    const int rowBase = blockIdx.x * 128;
    const int by = blockIdx.y;                 // 128-col tile: j in [32*by, +32)
    const int warpRow = (wid >> 1) * 32, warpCol = (wid & 1) * 64;

    float acc[2][8][4];
#pragma unroll
    for (int m = 0; m < 2; m++)
#pragma unroll
        for (int n = 0; n < 8; n++)
#pragma unroll
            for (int c = 0; c < 4; c++) acc[m][n][c] = 0.f;

    for (int chunk = 0; chunk < 4; chunk++) {
        const int k0 = chunk * 64;
        // A stage: BN(rec) for k<128, raw h for k>=128
        for (int idx = tid; idx < 1024; idx += 256) {
            int row = idx >> 3, i = idx & 7;
            int gk = k0 + i * 8;
            float4 v0, v1;
            if (k0 < HID) {
                const float* src = &g_rec[(size_t)(rowBase + row) * HID + gk];
                v0 = *(const float4*)src; v1 = *(const float4*)(src + 4);
                float4 a0 = *(const float4*)&g_bnA[gk], a1 = *(const float4*)&g_bnA[gk + 4];
                float4 b0 = *(const float4*)&g_bnB[gk], b1 = *(const float4*)&g_bnB[gk + 4];
                v0.x = fmaf(v0.x, a0.x, b0.x); v0.y = fmaf(v0.y, a0.y, b0.y);
                v0.z = fmaf(v0.z, a0.z, b0.z); v0.w = fmaf(v0.w, a0.w, b0.w);
                v1.x = fmaf(v1.x, a1.x, b1.x); v1.y = fmaf(v1.y, a1.y, b1.y);
                v1.z = fmaf(v1.z, a1.z, b1.z); v1.w = fmaf(v1.w, a1.w, b1.w);
            } else {
                const float* src = &hin[(size_t)(rowBase + row) * HID + (gk - HID)];
                v0 = *(const float4*)src; v1 = *(const float4*)(src + 4);
            }
            uint4 hi, lo; split8(v0, v1, hi, lo);
            uint32_t sw = SWZ((uint32_t)(row * 128 + i * 16));
            *(uint4*)(smp + T_A_HI + sw) = hi;
            *(uint4*)(smp + T_A_LO + sw) = lo;
        }
        // B stage: W2 rows [128*by, +128)
        for (int idx = tid; idx < 1024; idx += 256) {
            int row = idx >> 3, i = idx & 7;
            uint32_t sw = SWZ((uint32_t)(row * 128 + i * 16));
            int gi = (by * 128 + row) * 32 + (k0 >> 3) + i;
            *(uint4*)(smp + T_B_HI + sw) = ((const uint4*)g_W2h)[gi];
            *(uint4*)(smp + T_B_LO + sw) = ((const uint4*)g_W2l)[gi];
        }
        __syncthreads();
        chunk_compute(sb, warpRow, warpCol, lane, acc);
        __syncthreads();
    }

    // stage gate tile to smem (overlay dead A/B tiles), then fused LSTM pointwise
    float* Cs = (float*)smp;                   // 128 x 128 fp32 = 64KB
#pragma unroll
    for (int mt = 0; mt < 2; mt++) {
        int r0 = warpRow + mt * 16 + (lane >> 2);
#pragma unroll
        for (int n8 = 0; n8 < 8; n8++) {
            int col = warpCol + n8 * 8 + 2 * (lane & 3);
            float* c = acc[mt][n8];
            *(float2*)&Cs[r0 * 128 + col]       = make_float2(c[0], c[1]);
            *(float2*)&Cs[(r0 + 8) * 128 + col] = make_float2(c[2], c[3]);
        }
    }
    __syncthreads();
#pragma unroll
    for (int it = 0; it < 16; it++) {
        int cell = tid + 256 * it;
        int row = cell >> 5, jq = cell & 31;
        int grow = rowBase + row;
        int j = by * 32 + jq;
        float4 gt = *(const float4*)&Cs[row * 128 + jq * 4];   // i,f,g,o
        size_t idx = (size_t)grow * HID + j;
        float ig = gt.x + g_bias[j];
        float fg = gt.y + g_bias[HID + j];
        float gg = gt.z + g_bias[2 * HID + j];
        float og = gt.w + g_bias[3 * HID + j];
        float cn = sigf(fg) * g_c[idx] + sigf(ig) * tanhf(gg);
        g_c[idx] = cn;
        hout[idx] = sigf(og) * tanhf(cn);
    }
}

// ---------------- output: softmax(h @ W_out^T) ----------------
__global__ void out_kernel(const float* __restrict__ hin,
                           const float* __restrict__ W_out,
                           float* __restrict__ out) {
    int v = (blockIdx.x * blockDim.x + threadIdx.x) >> 5;
    int lane = threadIdx.x & 31;
    if (v >= N_VARS) return;
    float p0 = 0.f, p1 = 0.f, p2 = 0.f;
#pragma unroll
    for (int q = 0; q < 4; q++) {
        int col = lane + q * 32;
        float hv = hin[(size_t)v * HID + col];
        p0 = fmaf(hv, __ldg(&W_out[col]), p0);
        p1 = fmaf(hv, __ldg(&W_out[HID + col]), p1);
        p2 = fmaf(hv, __ldg(&W_out[2 * HID + col]), p2);
    }
#pragma unroll
    for (int o = 16; o > 0; o >>= 1) {
        p0 += __shfl_xor_sync(0xffffffffu, p0, o);
        p1 += __shfl_xor_sync(0xffffffffu, p1, o);
        p2 += __shfl_xor_sync(0xffffffffu, p2, o);
    }
    if (lane == 0) {
        float m = fmaxf(p0, fmaxf(p1, p2));
        float e0 = expf(p0 - m), e1 = expf(p1 - m), e2 = expf(p2 - m);
        float inv = 1.f / (e0 + e1 + e2);
        out[v * 3 + 0] = e0 * inv;
        out[v * 3 + 1] = e1 * inv;
        out[v * 3 + 2] = e2 * inv;
    }
}

// ---------------- launch ----------------
extern "C" void kernel_launch(void* const* d_in, const int* in_sizes, int n_in,
                              void* d_out, int out_size) {
    const float* h0      = (const float*)d_in[0];
    const float* var_reg = (const float*)d_in[1];
    const float* W_msg   = (const float*)d_in[2];
    const float* gamma   = (const float*)d_in[3];
    const float* beta    = (const float*)d_in[4];
    const float* W_ih    = (const float*)d_in[5];
    const float* W_hh    = (const float*)d_in[6];
    const float* b_ih    = (const float*)d_in[7];
    const float* b_hh    = (const float*)d_in[8];
    const float* W_out   = (const float*)d_in[9];
    const int*   ei      = (const int*)d_in[10];
    (void)in_sizes; (void)n_in;

    cudaFuncSetAttribute(rec_mma,   cudaFuncAttributeMaxDynamicSharedMemorySize, SMEMSZ);
    cudaFuncSetAttribute(gates_mma, cudaFuncAttributeMaxDynamicSharedMemorySize, SMEMSZ);

    float *hA, *hB, *cbuf, *agg, *deg, *stats;
    cudaGetSymbolAddress((void**)&hA, g_hA);
    cudaGetSymbolAddress((void**)&hB, g_hB);
    cudaGetSymbolAddress((void**)&cbuf, g_c);
    cudaGetSymbolAddress((void**)&agg, g_agg);
    cudaGetSymbolAddress((void**)&deg, g_degf);
    cudaGetSymbolAddress((void**)&stats, g_stats);

    cudaStream_t s = 0;
    cudaMemcpyAsync(hA, h0, (size_t)N_VARS * HID * sizeof(float),
                    cudaMemcpyDeviceToDevice, s);
    cudaMemsetAsync(hA + (size_t)N_VARS * HID, 0,
                    (size_t)(NP - N_VARS) * HID * sizeof(float), s);
    cudaMemsetAsync(cbuf, 0, (size_t)NP * HID * sizeof(float), s);
    cudaMemsetAsync(deg, 0, (size_t)NP * sizeof(float), s);

    prep_kernel<<<512, 256, 0, s>>>(W_msg, W_ih, W_hh, b_ih, b_hh);
    deg_kernel<<<(2 * N_EDGES + 255) / 256, 256, 0, s>>>(ei);

    const float* hin = hA;
    float* hout = hB;
    for (int st = 0; st < STEPS; ++st) {
        cudaMemsetAsync(agg, 0, (size_t)NP * HID * sizeof(float), s);
        cudaMemsetAsync(stats, 0, 2 * HID * sizeof(float), s);
        agg_kernel<<<N_EDGES / 8, 256, 0, s>>>(ei, hin);
        rec_mma<<<NBLK, 256, SMEMSZ, s>>>(hin, var_reg);
        stats_kernel<<<NBLK, 256, 0, s>>>();
        bn_finalize<<<1, HID, 0, s>>>(gamma, beta);
        gates_mma<<<dim3(NBLK, 4), 256, SMEMSZ, s>>>(hin, hout);
        const float* tmp = hout;
        hout = (float*)hin;
        hin = tmp;
    }
    out_kernel<<<(N_VARS * 32 + 255) / 256, 256, 0, s>>>(hin, W_out, (float*)d_out);
}

// round 5
// speedup vs baseline: 1.5589x; 1.4388x over previous
#include <cuda_runtime.h>
#include <cuda_bf16.h>
#include <math.h>
#include <stdint.h>

#define N_VARS 50000
#define HID 128
#define N_EDGES 400000
#define NP 50048            // 391 * 128
#define NBLK (NP / 128)     // 391
#define STEPS 4
#define BN_EPS 1e-5f

// ---------------- static device scratch ----------------
__device__ float g_hA[NP * HID];
__device__ float g_hB[NP * HID];
__device__ float g_c[NP * HID];
__device__ float g_agg[NP * HID];
__device__ float g_rec[NP * HID];
__device__ float g_degf[NP];
__device__ int   g_degi[NP];
__device__ int   g_off[NP + 1];
__device__ int   g_cur[NP];
__device__ int   g_adj[2 * N_EDGES];
__device__ __align__(16) __nv_bfloat16 g_W1h[128 * 256];   // rec weights  [n][k]
__device__ __align__(16) __nv_bfloat16 g_W1l[128 * 256];
__device__ __align__(16) __nv_bfloat16 g_W2h[512 * 256];   // gate weights [n=4j+g][k]
__device__ __align__(16) __nv_bfloat16 g_W2l[512 * 256];
__device__ __align__(16) __nv_bfloat16 g_X2h[NP * 256];    // [BN(rec)|h] hi
__device__ __align__(16) __nv_bfloat16 g_X2l[NP * 256];    // [BN(rec)|h] lo
__device__ float g_bias[4 * HID];
__device__ float g_stats[2 * HID];
__device__ __align__(16) float g_bnA[HID];
__device__ __align__(16) float g_bnB[HID];

__device__ __forceinline__ float sigf(float x) { return 1.0f / (1.0f + expf(-x)); }

__device__ __forceinline__ uint32_t smem_u32(const void* p) {
    uint32_t a;
    asm("{ .reg .u64 t; cvta.to.shared.u64 t, %1; cvt.u32.u64 %0, t; }" : "=r"(a) : "l"(p));
    return a;
}
#define SWZ(o) ((o) ^ (((o) >> 3) & 0x70))

#define LDSM4(R, A) \
    asm volatile("ldmatrix.sync.aligned.m8n8.x4.shared.b16 {%0,%1,%2,%3}, [%4];" \
                 : "=r"((R)[0]), "=r"((R)[1]), "=r"((R)[2]), "=r"((R)[3]) : "r"(A))

#define MMA(C, A, B0, B1) \
    asm volatile("mma.sync.aligned.m16n8k16.row.col.f32.bf16.bf16.f32 " \
                 "{%0,%1,%2,%3},{%4,%5,%6,%7},{%8,%9},{%0,%1,%2,%3};" \
                 : "+f"((C)[0]), "+f"((C)[1]), "+f"((C)[2]), "+f"((C)[3]) \
                 : "r"((A)[0]), "r"((A)[1]), "r"((A)[2]), "r"((A)[3]), "r"(B0), "r"(B1))

union Pack8 { __nv_bfloat16 b[8]; uint4 u; };
__device__ __forceinline__ void split8(float4 a, float4 b, uint4& hi, uint4& lo) {
    float v[8] = {a.x, a.y, a.z, a.w, b.x, b.y, b.z, b.w};
    Pack8 ph, pl;
#pragma unroll
    for (int i = 0; i < 8; i++) {
        __nv_bfloat16 h = __float2bfloat16(v[i]);
        ph.b[i] = h;
        pl.b[i] = __float2bfloat16(v[i] - __bfloat162float(h));
    }
    hi = ph.u; lo = pl.u;
}

// smem tiles: 128 rows x 64 bf16 (128B rows) each
#define T_A_HI 0
#define T_A_LO 16384
#define T_B_HI 32768
#define T_B_LO 49152
#define SMEMSZ (1024 + 65536)

// ---------------- prep: bf16-split weights, fused bias ----------------
__global__ void prep_kernel(const float* __restrict__ W_msg,
                            const float* __restrict__ W_ih,
                            const float* __restrict__ W_hh,
                            const float* __restrict__ b_ih,
                            const float* __restrict__ b_hh) {
    int t = blockIdx.x * blockDim.x + threadIdx.x;
    int stride = gridDim.x * blockDim.x;
    for (int i = t; i < 128 * 256; i += stride) {
        float w = W_msg[i];
        __nv_bfloat16 h = __float2bfloat16(w);
        g_W1h[i] = h;
        g_W1l[i] = __float2bfloat16(w - __bfloat162float(h));
    }
    for (int i = t; i < 512 * 256; i += stride) {
        int n = i >> 8, k = i & 255;
        int j = n >> 2, g = n & 3;
        int wrow = g * HID + j;
        float w = (k < HID) ? W_ih[wrow * HID + k] : W_hh[wrow * HID + (k - HID)];
        __nv_bfloat16 h = __float2bfloat16(w);
        g_W2h[i] = h;
        g_W2l[i] = __float2bfloat16(w - __bfloat162float(h));
    }
    for (int i = t; i < 4 * HID; i += stride) g_bias[i] = b_ih[i] + b_hh[i];
}

// ---------------- CSR build ----------------
__global__ void degcnt_kernel(const int* __restrict__ ei) {
    int i = blockIdx.x * blockDim.x + threadIdx.x;
    if (i < 2 * N_EDGES) atomicAdd(&g_degi[ei[i]], 1);
}

__global__ void scan_kernel() {       // single block, 1024 threads
    __shared__ int part[1024];
    int t = threadIdx.x;
    const int CH = (N_VARS + 1023) / 1024;   // 49
    int base = t * CH;
    int s = 0;
    for (int i = 0; i < CH; i++) {
        int idx = base + i;
        if (idx < N_VARS) s += g_degi[idx];
    }
    part[t] = s;
    __syncthreads();
    int val = s;
#pragma unroll
    for (int d = 1; d < 1024; d <<= 1) {
        int v = (t >= d) ? part[t - d] : 0;
        __syncthreads();
        part[t] += v;
        __syncthreads();
    }
    int excl = part[t] - val;
    int run = excl;
    for (int i = 0; i < CH; i++) {
        int idx = base + i;
        if (idx < N_VARS) {
            g_off[idx] = run;
            int d = g_degi[idx];
            g_degf[idx] = (float)d;
            run += d;
        }
    }
    if (t == 1023) g_off[N_VARS] = run;
}

__global__ void fill_kernel(const int* __restrict__ ei) {
    int i = blockIdx.x * blockDim.x + threadIdx.x;
    if (i >= 2 * N_EDGES) return;
    int s, d;
    if (i < N_EDGES) { s = ei[i]; d = ei[N_EDGES + i]; }
    else             { s = ei[i]; d = ei[i - N_EDGES]; }
    int pos = atomicAdd(&g_cur[d], 1);
    g_adj[g_off[d] + pos] = s;
}

// ---------------- CSR gather: agg[v] = sum_{u in adj(v)} h[u] ----------------
__global__ void gather_kernel(const float* __restrict__ hin) {
    int w = (blockIdx.x * blockDim.x + threadIdx.x) >> 5;
    int lane = threadIdx.x & 31;
    if (w >= N_VARS) return;
    int e = g_off[w], end = g_off[w + 1];
    int c4 = lane * 4;
    float4 s0 = make_float4(0, 0, 0, 0), s1 = make_float4(0, 0, 0, 0);
    for (; e + 2 <= end; e += 2) {
        int u0 = g_adj[e], u1 = g_adj[e + 1];
        float4 a = *(const float4*)&hin[(size_t)u0 * HID + c4];
        float4 b = *(const float4*)&hin[(size_t)u1 * HID + c4];
        s0.x += a.x; s0.y += a.y; s0.z += a.z; s0.w += a.w;
        s1.x += b.x; s1.y += b.y; s1.z += b.z; s1.w += b.w;
    }
    if (e < end) {
        int u = g_adj[e];
        float4 a = *(const float4*)&hin[(size_t)u * HID + c4];
        s0.x += a.x; s0.y += a.y; s0.z += a.z; s0.w += a.w;
    }
    s0.x += s1.x; s0.y += s1.y; s0.z += s1.z; s0.w += s1.w;
    *(float4*)&g_agg[(size_t)w * HID + c4] = s0;
}

// ---------------- warp-tile compute core (one K-chunk of 64), 32x32 warp tile ----------------
__device__ __forceinline__ void chunk_compute(uint32_t sb, int warpRow, int warpCol,
                                              int lane, float acc[2][4][4]) {
#pragma unroll
    for (int ks = 0; ks < 4; ks++) {
        uint32_t aH[2][4], aL[2][4];
#pragma unroll
        for (int mt = 0; mt < 2; mt++) {
            uint32_t off = (uint32_t)((warpRow + mt * 16 + (lane & 15)) * 128
                                      + ks * 32 + ((lane >> 4) & 1) * 16);
            uint32_t sw = SWZ(off);
            LDSM4(aH[mt], sb + T_A_HI + sw);
            LDSM4(aL[mt], sb + T_A_LO + sw);
        }
#pragma unroll
        for (int np = 0; np < 2; np++) {
            uint32_t bH[4], bL[4];
            uint32_t off = (uint32_t)((warpCol + np * 16 + ((lane >> 4) & 1) * 8 + (lane & 7)) * 128
                                      + ks * 32 + ((lane >> 3) & 1) * 16);
            uint32_t sw = SWZ(off);
            LDSM4(bH, sb + T_B_HI + sw);
            LDSM4(bL, sb + T_B_LO + sw);
#pragma unroll
            for (int mt = 0; mt < 2; mt++) {
#pragma unroll
                for (int nt = 0; nt < 2; nt++) {
                    float* c = acc[mt][np * 2 + nt];
                    MMA(c, aH[mt], bH[nt * 2], bH[nt * 2 + 1]);
                    MMA(c, aH[mt], bL[nt * 2], bL[nt * 2 + 1]);
                    MMA(c, aL[mt], bH[nt * 2], bH[nt * 2 + 1]);
                }
            }
        }
    }
}

// ---------------- rec = ([agg | deg*h] @ W1^T) * var_reg ----------------
__global__ void __launch_bounds__(512, 1)
rec_mma(const float* __restrict__ hin, const float* __restrict__ var_reg) {
    extern __shared__ char smraw[];
    uint32_t sb0 = smem_u32(smraw);
    uint32_t sb = (sb0 + 1023) & ~1023u;
    char* smp = smraw + (sb - sb0);
    const int tid = threadIdx.x;
    const int wid = tid >> 5, lane = tid & 31;
    const int rowBase = blockIdx.x * 128;
    const int warpRow = (wid >> 2) * 32, warpCol = (wid & 3) * 32;

    float acc[2][4][4];
#pragma unroll
    for (int m = 0; m < 2; m++)
#pragma unroll
        for (int n = 0; n < 4; n++)
#pragma unroll
            for (int c = 0; c < 4; c++) acc[m][n][c] = 0.f;

    for (int chunk = 0; chunk < 4; chunk++) {
        const int k0 = chunk * 64;
        for (int idx = tid; idx < 1024; idx += 512) {
            int row = idx >> 3, i = idx & 7;
            int gk = k0 + i * 8;
            float4 v0, v1;
            if (k0 < HID) {
                const float* src = &g_agg[(size_t)(rowBase + row) * HID + gk];
                v0 = *(const float4*)src; v1 = *(const float4*)(src + 4);
            } else {
                const float* src = &hin[(size_t)(rowBase + row) * HID + (gk - HID)];
                v0 = *(const float4*)src; v1 = *(const float4*)(src + 4);
                float d = g_degf[rowBase + row];
                v0.x *= d; v0.y *= d; v0.z *= d; v0.w *= d;
                v1.x *= d; v1.y *= d; v1.z *= d; v1.w *= d;
            }
            uint4 hi, lo; split8(v0, v1, hi, lo);
            uint32_t sw = SWZ((uint32_t)(row * 128 + i * 16));
            *(uint4*)(smp + T_A_HI + sw) = hi;
            *(uint4*)(smp + T_A_LO + sw) = lo;
        }
        for (int idx = tid; idx < 1024; idx += 512) {
            int row = idx >> 3, i = idx & 7;
            uint32_t sw = SWZ((uint32_t)(row * 128 + i * 16));
            int gi = row * 32 + (k0 >> 3) + i;
            *(uint4*)(smp + T_B_HI + sw) = ((const uint4*)g_W1h)[gi];
            *(uint4*)(smp + T_B_LO + sw) = ((const uint4*)g_W1l)[gi];
        }
        __syncthreads();
        chunk_compute(sb, warpRow, warpCol, lane, acc);
        __syncthreads();
    }

#pragma unroll
    for (int mt = 0; mt < 2; mt++) {
        int r0 = rowBase + warpRow + mt * 16 + (lane >> 2);
        int r1 = r0 + 8;
        float vr0 = (r0 < N_VARS) ? var_reg[r0] : 0.f;
        float vr1 = (r1 < N_VARS) ? var_reg[r1] : 0.f;
#pragma unroll
        for (int n8 = 0; n8 < 4; n8++) {
            int col = warpCol + n8 * 8 + 2 * (lane & 3);
            float* c = acc[mt][n8];
            *(float2*)&g_rec[(size_t)r0 * HID + col] = make_float2(c[0] * vr0, c[1] * vr0);
            *(float2*)&g_rec[(size_t)r1 * HID + col] = make_float2(c[2] * vr1, c[3] * vr1);
        }
    }
}

// ---------------- column stats of rec ----------------
__global__ void stats_kernel() {
    int tid = threadIdx.x;
    int tx = tid & 31, ty = tid >> 5;
    int rowBase = blockIdx.x * 128 + ty * 16;
    float s[4] = {0, 0, 0, 0}, s2[4] = {0, 0, 0, 0};
#pragma unroll
    for (int i = 0; i < 16; i++) {
        float4 v = *(const float4*)&g_rec[(size_t)(rowBase + i) * HID + tx * 4];
        s[0] += v.x; s[1] += v.y; s[2] += v.z; s[3] += v.w;
        s2[0] += v.x * v.x; s2[1] += v.y * v.y; s2[2] += v.z * v.z; s2[3] += v.w * v.w;
    }
#pragma unroll
    for (int c = 0; c < 4; c++) {
        atomicAdd(&g_stats[tx * 4 + c], s[c]);
        atomicAdd(&g_stats[HID + tx * 4 + c], s2[c]);
    }
}

__global__ void bn_finalize(const float* __restrict__ gamma, const float* __restrict__ beta) {
    int j = threadIdx.x;
    float sum = g_stats[j], sq = g_stats[HID + j];
    float mean = sum * (1.0f / N_VARS);
    float var = sq * (1.0f / N_VARS) - mean * mean;
    float a = gamma[j] * rsqrtf(var + BN_EPS);
    g_bnA[j] = a;
    g_bnB[j] = beta[j] - mean * a;
    g_stats[j] = 0.f;            // reset for next step
    g_stats[HID + j] = 0.f;
}

// ---------------- X2 = bf16-split of [BN(rec) | h] ----------------
__global__ void x2_convert(const float* __restrict__ hin) {
    int idx = blockIdx.x * blockDim.x + threadIdx.x;   // one per 8 k-values
    if (idx >= NP * 32) return;
    int row = idx >> 5;
    int k = (idx & 31) * 8;
    float4 v0, v1;
    if (k < HID) {
        const float* src = &g_rec[(size_t)row * HID + k];
        v0 = *(const float4*)src; v1 = *(const float4*)(src + 4);
        float4 a0 = *(const float4*)&g_bnA[k], a1 = *(const float4*)&g_bnA[k + 4];
        float4 b0 = *(const float4*)&g_bnB[k], b1 = *(const float4*)&g_bnB[k + 4];
        v0.x = fmaf(v0.x, a0.x, b0.x); v0.y = fmaf(v0.y, a0.y, b0.y);
        v0.z = fmaf(v0.z, a0.z, b0.z); v0.w = fmaf(v0.w, a0.w, b0.w);
        v1.x = fmaf(v1.x, a1.x, b1.x); v1.y = fmaf(v1.y, a1.y, b1.y);
        v1.z = fmaf(v1.z, a1.z, b1.z); v1.w = fmaf(v1.w, a1.w, b1.w);
    } else {
        const float* src = &hin[(size_t)row * HID + (k - HID)];
        v0 = *(const float4*)src; v1 = *(const float4*)(src + 4);
    }
    uint4 hi, lo; split8(v0, v1, hi, lo);
    ((uint4*)g_X2h)[idx] = hi;
    ((uint4*)g_X2l)[idx] = lo;
}

// ---------------- gates = X2 @ W2^T + LSTM pointwise ----------------
__global__ void __launch_bounds__(512, 1)
gates_mma(float* __restrict__ hout) {
    extern __shared__ char smraw[];
    uint32_t sb0 = smem_u32(smraw);
    uint32_t sb = (sb0 + 1023) & ~1023u;
    char* smp = smraw + (sb - sb0);
    const int tid = threadIdx.x;
    const int wid = tid >> 5, lane = tid & 31;
    const int rowBase = blockIdx.x * 128;
    const int by = blockIdx.y;
    const int warpRow = (wid >> 2) * 32, warpCol = (wid & 3) * 32;

    float acc[2][4][4];
#pragma unroll
    for (int m = 0; m < 2; m++)
#pragma unroll
        for (int n = 0; n < 4; n++)
#pragma unroll
            for (int c = 0; c < 4; c++) acc[m][n][c] = 0.f;

    for (int chunk = 0; chunk < 4; chunk++) {
        const int k0 = chunk * 64;
        for (int idx = tid; idx < 1024; idx += 512) {
            int row = idx >> 3, i = idx & 7;
            int gi = (rowBase + row) * 32 + (k0 >> 3) + i;
            uint32_t sw = SWZ((uint32_t)(row * 128 + i * 16));
            *(uint4*)(smp + T_A_HI + sw) = ((const uint4*)g_X2h)[gi];
            *(uint4*)(smp + T_A_LO + sw) = ((const uint4*)g_X2l)[gi];
        }
        for (int idx = tid; idx < 1024; idx += 512) {
            int row = idx >> 3, i = idx & 7;
            uint32_t sw = SWZ((uint32_t)(row * 128 + i * 16));
            int gi = (by * 128 + row) * 32 + (k0 >> 3) + i;
            *(uint4*)(smp + T_B_HI + sw) = ((const uint4*)g_W2h)[gi];
            *(uint4*)(smp + T_B_LO + sw) = ((const uint4*)g_W2l)[gi];
        }
        __syncthreads();
        chunk_compute(sb, warpRow, warpCol, lane, acc);
        __syncthreads();
    }

    float* Cs = (float*)smp;                   // 128 x 128 fp32 overlay
#pragma unroll
    for (int mt = 0; mt < 2; mt++) {
        int r0 = warpRow + mt * 16 + (lane >> 2);
#pragma unroll
        for (int n8 = 0; n8 < 4; n8++) {
            int col = warpCol + n8 * 8 + 2 * (lane & 3);
            float* c = acc[mt][n8];
            *(float2*)&Cs[r0 * 128 + col]       = make_float2(c[0], c[1]);
            *(float2*)&Cs[(r0 + 8) * 128 + col] = make_float2(c[2], c[3]);
        }
    }
    __syncthreads();
#pragma unroll
    for (int it = 0; it < 8; it++) {
        int cell = tid + 512 * it;
        int row = cell >> 5, jq = cell & 31;
        int grow = rowBase + row;
        int j = by * 32 + jq;
        float4 gt = *(const float4*)&Cs[row * 128 + jq * 4];   // i,f,g,o
        size_t idx = (size_t)grow * HID + j;
        float ig = gt.x + g_bias[j];
        float fg = gt.y + g_bias[HID + j];
        float gg = gt.z + g_bias[2 * HID + j];
        float og = gt.w + g_bias[3 * HID + j];
        float cn = sigf(fg) * g_c[idx] + sigf(ig) * tanhf(gg);
        g_c[idx] = cn;
        hout[idx] = sigf(og) * tanhf(cn);
    }
}

// ---------------- output: softmax(h @ W_out^T) ----------------
__global__ void out_kernel(const float* __restrict__ hin,
                           const float* __restrict__ W_out,
                           float* __restrict__ out) {
    int v = (blockIdx.x * blockDim.x + threadIdx.x) >> 5;
    int lane = threadIdx.x & 31;
    if (v >= N_VARS) return;
    float p0 = 0.f, p1 = 0.f, p2 = 0.f;
#pragma unroll
    for (int q = 0; q < 4; q++) {
        int col = lane + q * 32;
        float hv = hin[(size_t)v * HID + col];
        p0 = fmaf(hv, __ldg(&W_out[col]), p0);
        p1 = fmaf(hv, __ldg(&W_out[HID + col]), p1);
        p2 = fmaf(hv, __ldg(&W_out[2 * HID + col]), p2);
    }
#pragma unroll
    for (int o = 16; o > 0; o >>= 1) {
        p0 += __shfl_xor_sync(0xffffffffu, p0, o);
        p1 += __shfl_xor_sync(0xffffffffu, p1, o);
        p2 += __shfl_xor_sync(0xffffffffu, p2, o);
    }
    if (lane == 0) {
        float m = fmaxf(p0, fmaxf(p1, p2));
        float e0 = expf(p0 - m), e1 = expf(p1 - m), e2 = expf(p2 - m);
        float inv = 1.f / (e0 + e1 + e2);
        out[v * 3 + 0] = e0 * inv;
        out[v * 3 + 1] = e1 * inv;
        out[v * 3 + 2] = e2 * inv;
    }
}

// ---------------- launch ----------------
extern "C" void kernel_launch(void* const* d_in, const int* in_sizes, int n_in,
                              void* d_out, int out_size) {
    const float* h0      = (const float*)d_in[0];
    const float* var_reg = (const float*)d_in[1];
    const float* W_msg   = (const float*)d_in[2];
    const float* gamma   = (const float*)d_in[3];
    const float* beta    = (const float*)d_in[4];
    const float* W_ih    = (const float*)d_in[5];
    const float* W_hh    = (const float*)d_in[6];
    const float* b_ih    = (const float*)d_in[7];
    const float* b_hh    = (const float*)d_in[8];
    const float* W_out   = (const float*)d_in[9];
    const int*   ei      = (const int*)d_in[10];
    (void)in_sizes; (void)n_in;

    cudaFuncSetAttribute(rec_mma,   cudaFuncAttributeMaxDynamicSharedMemorySize, SMEMSZ);
    cudaFuncSetAttribute(gates_mma, cudaFuncAttributeMaxDynamicSharedMemorySize, SMEMSZ);

    float *hA, *hB, *cbuf;
    int *degi, *cur;
    cudaGetSymbolAddress((void**)&hA, g_hA);
    cudaGetSymbolAddress((void**)&hB, g_hB);
    cudaGetSymbolAddress((void**)&cbuf, g_c);
    cudaGetSymbolAddress((void**)&degi, g_degi);
    cudaGetSymbolAddress((void**)&cur, g_cur);

    cudaStream_t s = 0;
    cudaMemcpyAsync(hA, h0, (size_t)N_VARS * HID * sizeof(float),
                    cudaMemcpyDeviceToDevice, s);
    cudaMemsetAsync(hA + (size_t)N_VARS * HID, 0,
                    (size_t)(NP - N_VARS) * HID * sizeof(float), s);
    cudaMemsetAsync(cbuf, 0, (size_t)NP * HID * sizeof(float), s);
    cudaMemsetAsync(degi, 0, (size_t)NP * sizeof(int), s);
    cudaMemsetAsync(cur, 0, (size_t)NP * sizeof(int), s);

    prep_kernel<<<512, 256, 0, s>>>(W_msg, W_ih, W_hh, b_ih, b_hh);
    degcnt_kernel<<<(2 * N_EDGES + 255) / 256, 256, 0, s>>>(ei);
    scan_kernel<<<1, 1024, 0, s>>>();
    fill_kernel<<<(2 * N_EDGES + 255) / 256, 256, 0, s>>>(ei);

    const float* hin = hA;
    float* hout = hB;
    for (int st = 0; st < STEPS; ++st) {
        gather_kernel<<<(N_VARS * 32 + 255) / 256, 256, 0, s>>>(hin);
        rec_mma<<<NBLK, 512, SMEMSZ, s>>>(hin, var_reg);
        stats_kernel<<<NBLK, 256, 0, s>>>();
        bn_finalize<<<1, HID, 0, s>>>(gamma, beta);
        x2_convert<<<(NP * 32 + 255) / 256, 256, 0, s>>>(hin);
        gates_mma<<<dim3(NBLK, 4), 512, SMEMSZ, s>>>(hout);
        const float* tmp = hout;
        hout = (float*)hin;
        hin = tmp;
    }
    out_kernel<<<(N_VARS * 32 + 255) / 256, 256, 0, s>>>(hin, W_out, (float*)d_out);
}

// round 7
// speedup vs baseline: 2.4959x; 1.6011x over previous
#include <cuda_runtime.h>
#include <cuda_bf16.h>
#include <math.h>
#include <stdint.h>

#define N_VARS 50000
#define HID 128
#define N_EDGES 400000
#define NP 50048            // 391 * 128
#define NBLK (NP / 128)     // 391
#define STEPS 4
#define BN_EPS 1e-5f

// ---------------- static device scratch ----------------
__device__ float g_hA[NP * HID];
__device__ float g_hB[NP * HID];
__device__ float g_c[NP * HID];
__device__ float g_rec[NP * HID];
__device__ float g_degf[NP];
__device__ int   g_degi[NP];
__device__ int   g_off[NP + 1];
__device__ int   g_cur[NP];
__device__ int   g_adj[2 * N_EDGES];
__device__ __align__(16) __nv_bfloat16 g_W1h[128 * 256];   // rec weights  [n][k]
__device__ __align__(16) __nv_bfloat16 g_W1l[128 * 256];
__device__ __align__(16) __nv_bfloat16 g_W2h[512 * 256];   // gate weights [n=4j+g][k]
__device__ __align__(16) __nv_bfloat16 g_W2l[512 * 256];
__device__ __align__(16) __nv_bfloat16 g_X1h[NP * 256];    // [agg | deg*h] hi
__device__ __align__(16) __nv_bfloat16 g_X1l[NP * 256];
// ping-pong buffers: [BN(rec) | h] — gates reads par, writes h-half of par^1
__device__ __align__(16) __nv_bfloat16 g_X2h[2][NP * 256];
__device__ __align__(16) __nv_bfloat16 g_X2l[2][NP * 256];
__device__ float g_bias[4 * HID];
__device__ float g_stats[2 * HID];
__device__ __align__(16) float g_bnA[HID];
__device__ __align__(16) float g_bnB[HID];

__device__ __forceinline__ float sigf(float x) { return 1.0f / (1.0f + expf(-x)); }

__device__ __forceinline__ uint32_t smem_u32(const void* p) {
    uint32_t a;
    asm("{ .reg .u64 t; cvta.to.shared.u64 t, %1; cvt.u32.u64 %0, t; }" : "=r"(a) : "l"(p));
    return a;
}
#define SWZ(o) ((o) ^ (((o) >> 3) & 0x70))

#define LDSM4(R, A) \
    asm volatile("ldmatrix.sync.aligned.m8n8.x4.shared.b16 {%0,%1,%2,%3}, [%4];" \
                 : "=r"((R)[0]), "=r"((R)[1]), "=r"((R)[2]), "=r"((R)[3]) : "r"(A))

#define MMA(C, A, B0, B1) \
    asm volatile("mma.sync.aligned.m16n8k16.row.col.f32.bf16.bf16.f32 " \
                 "{%0,%1,%2,%3},{%4,%5,%6,%7},{%8,%9},{%0,%1,%2,%3};" \
                 : "+f"((C)[0]), "+f"((C)[1]), "+f"((C)[2]), "+f"((C)[3]) \
                 : "r"((A)[0]), "r"((A)[1]), "r"((A)[2]), "r"((A)[3]), "r"(B0), "r"(B1))

#define CP16(dst_u32, src_ptr) \
    asm volatile("cp.async.cg.shared.global [%0], [%1], 16;" \
                 :: "r"(dst_u32), "l"(src_ptr))
#define CP_COMMIT() asm volatile("cp.async.commit_group;")
#define CP_WAIT(n)  asm volatile("cp.async.wait_group %0;" :: "n"(n))

union Pack8 { __nv_bfloat16 b[8]; uint4 u; };
__device__ __forceinline__ void split8(float4 a, float4 b, uint4& hi, uint4& lo) {
    float v[8] = {a.x, a.y, a.z, a.w, b.x, b.y, b.z, b.w};
    Pack8 ph, pl;
#pragma unroll
    for (int i = 0; i < 8; i++) {
        __nv_bfloat16 h = __float2bfloat16(v[i]);
        ph.b[i] = h;
        pl.b[i] = __float2bfloat16(v[i] - __bfloat162float(h));
    }
    hi = ph.u; lo = pl.u;
}
union Pack4 { __nv_bfloat16 b[4]; uint2 u; };
__device__ __forceinline__ void split4(float4 a, uint2& hi, uint2& lo) {
    float v[4] = {a.x, a.y, a.z, a.w};
    Pack4 ph, pl;
#pragma unroll
    for (int i = 0; i < 4; i++) {
        __nv_bfloat16 h = __float2bfloat16(v[i]);
        ph.b[i] = h;
        pl.b[i] = __float2bfloat16(v[i] - __bfloat162float(h));
    }
    hi = ph.u; lo = pl.u;
}

// smem: 2 stages x (A_hi, A_lo, B_hi, B_lo), each tile 128x64 bf16 = 16KB
#define T_A_HI 0
#define T_A_LO 16384
#define T_B_HI 32768
#define T_B_LO 49152
#define STAGE_SZ 65536
#define SMEMSZ (1024 + 2 * STAGE_SZ)

// ---------------- prep: bf16-split weights, fused bias ----------------
__global__ void prep_kernel(const float* __restrict__ W_msg,
                            const float* __restrict__ W_ih,
                            const float* __restrict__ W_hh,
                            const float* __restrict__ b_ih,
                            const float* __restrict__ b_hh) {
    int t = blockIdx.x * blockDim.x + threadIdx.x;
    int stride = gridDim.x * blockDim.x;
    for (int i = t; i < 128 * 256; i += stride) {
        float w = W_msg[i];
        __nv_bfloat16 h = __float2bfloat16(w);
        g_W1h[i] = h;
        g_W1l[i] = __float2bfloat16(w - __bfloat162float(h));
    }
    for (int i = t; i < 512 * 256; i += stride) {
        int n = i >> 8, k = i & 255;
        int j = n >> 2, g = n & 3;
        int wrow = g * HID + j;
        float w = (k < HID) ? W_ih[wrow * HID + k] : W_hh[wrow * HID + (k - HID)];
        __nv_bfloat16 h = __float2bfloat16(w);
        g_W2h[i] = h;
        g_W2l[i] = __float2bfloat16(w - __bfloat162float(h));
    }
    for (int i = t; i < 4 * HID; i += stride) g_bias[i] = b_ih[i] + b_hh[i];
}

// ---------------- CSR build ----------------
__global__ void degcnt_kernel(const int* __restrict__ ei) {
    int i = blockIdx.x * blockDim.x + threadIdx.x;
    if (i < 2 * N_EDGES) atomicAdd(&g_degi[ei[i]], 1);
}

__global__ void scan_kernel() {       // single block, 1024 threads
    __shared__ int part[1024];
    int t = threadIdx.x;
    const int CH = (N_VARS + 1023) / 1024;
    int base = t * CH;
    int s = 0;
    for (int i = 0; i < CH; i++) {
        int idx = base + i;
        if (idx < N_VARS) s += g_degi[idx];
    }
    part[t] = s;
    __syncthreads();
    int val = s;
#pragma unroll
    for (int d = 1; d < 1024; d <<= 1) {
        int v = (t >= d) ? part[t - d] : 0;
        __syncthreads();
        part[t] += v;
        __syncthreads();
    }
    int excl = part[t] - val;
    int run = excl;
    for (int i = 0; i < CH; i++) {
        int idx = base + i;
        if (idx < N_VARS) {
            g_off[idx] = run;
            int d = g_degi[idx];
            g_degf[idx] = (float)d;
            run += d;
        }
    }
    if (t == 1023) g_off[N_VARS] = run;
}

__global__ void fill_kernel(const int* __restrict__ ei) {
    int i = blockIdx.x * blockDim.x + threadIdx.x;
    if (i >= 2 * N_EDGES) return;
    int s, d;
    if (i < N_EDGES) { s = ei[i]; d = ei[N_EDGES + i]; }
    else             { s = ei[i]; d = ei[i - N_EDGES]; }
    int pos = atomicAdd(&g_cur[d], 1);
    g_adj[g_off[d] + pos] = s;
}

// ---------------- h0 split -> X2[0] h-part (once) ----------------
__global__ void h0split(const float* __restrict__ hin) {
    int idx = blockIdx.x * blockDim.x + threadIdx.x;   // one per 8 k-values
    if (idx >= NP * 16) return;
    int row = idx >> 4, i = idx & 15;
    const float* src = &hin[(size_t)row * HID + i * 8];
    float4 v0 = *(const float4*)src, v1 = *(const float4*)(src + 4);
    uint4 hi, lo; split8(v0, v1, hi, lo);
    ((uint4*)g_X2h[0])[row * 32 + 16 + i] = hi;
    ((uint4*)g_X2l[0])[row * 32 + 16 + i] = lo;
}

// ---------------- CSR gather -> X1 = split([agg | deg*h]) ----------------
__global__ void gather_kernel(const float* __restrict__ hin) {
    int w = (blockIdx.x * blockDim.x + threadIdx.x) >> 5;
    int lane = threadIdx.x & 31;
    if (w >= N_VARS) return;
    int e = g_off[w], end = g_off[w + 1];
    int c4 = lane * 4;
    float4 s0 = make_float4(0, 0, 0, 0), s1 = make_float4(0, 0, 0, 0);
    for (; e + 2 <= end; e += 2) {
        int u0 = g_adj[e], u1 = g_adj[e + 1];
        float4 a = *(const float4*)&hin[(size_t)u0 * HID + c4];
        float4 b = *(const float4*)&hin[(size_t)u1 * HID + c4];
        s0.x += a.x; s0.y += a.y; s0.z += a.z; s0.w += a.w;
        s1.x += b.x; s1.y += b.y; s1.z += b.z; s1.w += b.w;
    }
    if (e < end) {
        int u = g_adj[e];
        float4 a = *(const float4*)&hin[(size_t)u * HID + c4];
        s0.x += a.x; s0.y += a.y; s0.z += a.z; s0.w += a.w;
    }
    s0.x += s1.x; s0.y += s1.y; s0.z += s1.z; s0.w += s1.w;
    uint2 hi, lo;
    split4(s0, hi, lo);
    ((uint2*)g_X1h)[w * 64 + lane] = hi;        // k = c4
    ((uint2*)g_X1l)[w * 64 + lane] = lo;
    // deg * h part
    float d = g_degf[w];
    float4 hv = *(const float4*)&hin[(size_t)w * HID + c4];
    hv.x *= d; hv.y *= d; hv.z *= d; hv.w *= d;
    split4(hv, hi, lo);
    ((uint2*)g_X1h)[w * 64 + 32 + lane] = hi;   // k = 128 + c4
    ((uint2*)g_X1l)[w * 64 + 32 + lane] = lo;
}

// ---------------- cp.async tile staging ----------------
__device__ __forceinline__ void stage_tiles(uint32_t sbase,
                                            const uint4* __restrict__ Ah,
                                            const uint4* __restrict__ Al,
                                            const uint4* __restrict__ Bh,
                                            const uint4* __restrict__ Bl,
                                            int aBase32, int bBase32, int k8, int tid) {
#pragma unroll
    for (int idx = tid; idx < 1024; idx += 512) {
        int row = idx >> 3, i = idx & 7;
        uint32_t sw = SWZ((uint32_t)(row * 128 + i * 16));
        int ga = aBase32 + row * 32 + k8 + i;
        int gb = bBase32 + row * 32 + k8 + i;
        CP16(sbase + T_A_HI + sw, Ah + ga);
        CP16(sbase + T_A_LO + sw, Al + ga);
        CP16(sbase + T_B_HI + sw, Bh + gb);
        CP16(sbase + T_B_LO + sw, Bl + gb);
    }
}

// ---------------- warp-tile compute core (one K-chunk of 64), 32x32 warp tile ----------------
__device__ __forceinline__ void chunk_compute(uint32_t sb, int warpRow, int warpCol,
                                              int lane, float acc[2][4][4]) {
#pragma unroll
    for (int ks = 0; ks < 4; ks++) {
        uint32_t aH[2][4], aL[2][4];
#pragma unroll
        for (int mt = 0; mt < 2; mt++) {
            uint32_t off = (uint32_t)((warpRow + mt * 16 + (lane & 15)) * 128
                                      + ks * 32 + ((lane >> 4) & 1) * 16);
            uint32_t sw = SWZ(off);
            LDSM4(aH[mt], sb + T_A_HI + sw);
            LDSM4(aL[mt], sb + T_A_LO + sw);
        }
#pragma unroll
        for (int np = 0; np < 2; np++) {
            uint32_t bH[4], bL[4];
            uint32_t off = (uint32_t)((warpCol + np * 16 + ((lane >> 4) & 1) * 8 + (lane & 7)) * 128
                                      + ks * 32 + ((lane >> 3) & 1) * 16);
            uint32_t sw = SWZ(off);
            LDSM4(bH, sb + T_B_HI + sw);
            LDSM4(bL, sb + T_B_LO + sw);
#pragma unroll
            for (int mt = 0; mt < 2; mt++) {
#pragma unroll
                for (int nt = 0; nt < 2; nt++) {
                    float* c = acc[mt][np * 2 + nt];
                    MMA(c, aH[mt], bH[nt * 2], bH[nt * 2 + 1]);
                    MMA(c, aH[mt], bL[nt * 2], bL[nt * 2 + 1]);
                    MMA(c, aL[mt], bH[nt * 2], bH[nt * 2 + 1]);
                }
            }
        }
    }
}

// ---------------- shared GEMM pipeline ----------------
#define GEMM_PIPELINE(Ah, Al, Bh, Bl, ABASE, BBASE)                                   \
    stage_tiles(sb, Ah, Al, Bh, Bl, ABASE, BBASE, 0, tid);  CP_COMMIT();              \
    stage_tiles(sb + STAGE_SZ, Ah, Al, Bh, Bl, ABASE, BBASE, 8, tid); CP_COMMIT();    \
    _Pragma("unroll")                                                                 \
    for (int c = 0; c < 4; c++) {                                                     \
        if (c < 3) { CP_WAIT(1); } else { CP_WAIT(0); }                               \
        __syncthreads();                                                              \
        chunk_compute(sb + (c & 1) * STAGE_SZ, warpRow, warpCol, lane, acc);          \
        __syncthreads();                                                              \
        if (c < 2) {                                                                  \
            stage_tiles(sb + (c & 1) * STAGE_SZ, Ah, Al, Bh, Bl,                      \
                        ABASE, BBASE, (c + 2) * 8, tid);                              \
            CP_COMMIT();                                                              \
        }                                                                             \
    }

// ---------------- rec = (X1 @ W1^T) * var_reg, with fused BN stats ----------------
__global__ void __launch_bounds__(512, 1)
rec_mma(const float* __restrict__ var_reg) {
    extern __shared__ char smraw[];
    uint32_t sb0 = smem_u32(smraw);
    uint32_t sb = (sb0 + 1023) & ~1023u;
    const int tid = threadIdx.x;
    const int wid = tid >> 5, lane = tid & 31;
    const int rowBase = blockIdx.x * 128;
    const int warpRow = (wid >> 2) * 32, warpCol = (wid & 3) * 32;

    float acc[2][4][4];
#pragma unroll
    for (int m = 0; m < 2; m++)
#pragma unroll
        for (int n = 0; n < 4; n++)
#pragma unroll
            for (int c = 0; c < 4; c++) acc[m][n][c] = 0.f;

    GEMM_PIPELINE((const uint4*)g_X1h, (const uint4*)g_X1l,
                  (const uint4*)g_W1h, (const uint4*)g_W1l,
                  rowBase * 32, 0)

    // epilogue: scale by var_reg, store rec, fused column stats
    float s[4][2] = {}, q[4][2] = {};
#pragma unroll
    for (int mt = 0; mt < 2; mt++) {
        int r0 = rowBase + warpRow + mt * 16 + (lane >> 2);
        int r1 = r0 + 8;
        float vr0 = (r0 < N_VARS) ? var_reg[r0] : 0.f;
        float vr1 = (r1 < N_VARS) ? var_reg[r1] : 0.f;
#pragma unroll
        for (int n8 = 0; n8 < 4; n8++) {
            int col = warpCol + n8 * 8 + 2 * (lane & 3);
            float* c = acc[mt][n8];
            float v00 = c[0] * vr0, v01 = c[1] * vr0;
            float v10 = c[2] * vr1, v11 = c[3] * vr1;
            *(float2*)&g_rec[(size_t)r0 * HID + col] = make_float2(v00, v01);
            *(float2*)&g_rec[(size_t)r1 * HID + col] = make_float2(v10, v11);
            s[n8][0] += v00 + v10;  q[n8][0] += v00 * v00 + v10 * v10;
            s[n8][1] += v01 + v11;  q[n8][1] += v01 * v01 + v11 * v11;
        }
    }
#pragma unroll
    for (int o = 4; o <= 16; o <<= 1) {
#pragma unroll
        for (int n8 = 0; n8 < 4; n8++) {
#pragma unroll
            for (int p = 0; p < 2; p++) {
                s[n8][p] += __shfl_xor_sync(0xffffffffu, s[n8][p], o);
                q[n8][p] += __shfl_xor_sync(0xffffffffu, q[n8][p], o);
            }
        }
    }
    if (lane < 4) {
#pragma unroll
        for (int n8 = 0; n8 < 4; n8++) {
#pragma unroll
            for (int p = 0; p < 2; p++) {
                int col = warpCol + n8 * 8 + 2 * lane + p;
                atomicAdd(&g_stats[col], s[n8][p]);
                atomicAdd(&g_stats[HID + col], q[n8][p]);
            }
        }
    }
}

__global__ void bn_finalize(const float* __restrict__ gamma, const float* __restrict__ beta) {
    int j = threadIdx.x;
    float sum = g_stats[j], sq = g_stats[HID + j];
    float mean = sum * (1.0f / N_VARS);
    float var = sq * (1.0f / N_VARS) - mean * mean;
    float a = gamma[j] * rsqrtf(var + BN_EPS);
    g_bnA[j] = a;
    g_bnB[j] = beta[j] - mean * a;
    g_stats[j] = 0.f;            // reset for next step / next replay
    g_stats[HID + j] = 0.f;
}

// ---------------- X2[par] rec-half = bf16-split of BN(rec) ----------------
__global__ void x2_convert(int par) {
    int idx = blockIdx.x * blockDim.x + threadIdx.x;   // one per 8 k-values, k<128
    if (idx >= NP * 16) return;
    int row = idx >> 4;
    int k = (idx & 15) * 8;
    const float* src = &g_rec[(size_t)row * HID + k];
    float4 v0 = *(const float4*)src, v1 = *(const float4*)(src + 4);
    float4 a0 = *(const float4*)&g_bnA[k], a1 = *(const float4*)&g_bnA[k + 4];
    float4 b0 = *(const float4*)&g_bnB[k], b1 = *(const float4*)&g_bnB[k + 4];
    v0.x = fmaf(v0.x, a0.x, b0.x); v0.y = fmaf(v0.y, a0.y, b0.y);
    v0.z = fmaf(v0.z, a0.z, b0.z); v0.w = fmaf(v0.w, a0.w, b0.w);
    v1.x = fmaf(v1.x, a1.x, b1.x); v1.y = fmaf(v1.y, a1.y, b1.y);
    v1.z = fmaf(v1.z, a1.z, b1.z); v1.w = fmaf(v1.w, a1.w, b1.w);
    uint4 hi, lo; split8(v0, v1, hi, lo);
    ((uint4*)g_X2h[par])[row * 32 + (idx & 15)] = hi;
    ((uint4*)g_X2l[par])[row * 32 + (idx & 15)] = lo;
}

// ---------------- gates = X2[par] @ W2^T + LSTM pointwise; split(h) -> X2[par^1] ----------------
__global__ void __launch_bounds__(512, 1)
gates_mma(float* __restrict__ hout, int par) {
    extern __shared__ char smraw[];
    uint32_t sb0 = smem_u32(smraw);
    uint32_t sb = (sb0 + 1023) & ~1023u;
    char* smp = smraw + (sb - sb0);
    const int tid = threadIdx.x;
    const int wid = tid >> 5, lane = tid & 31;
    const int rowBase = blockIdx.x * 128;
    const int by = blockIdx.y;
    const int warpRow = (wid >> 2) * 32, warpCol = (wid & 3) * 32;

    float acc[2][4][4];
#pragma unroll
    for (int m = 0; m < 2; m++)
#pragma unroll
        for (int n = 0; n < 4; n++)
#pragma unroll
            for (int c = 0; c < 4; c++) acc[m][n][c] = 0.f;

    GEMM_PIPELINE((const uint4*)g_X2h[par], (const uint4*)g_X2l[par],
                  (const uint4*)g_W2h, (const uint4*)g_W2l,
                  rowBase * 32, by * 128 * 32)

    // stage gate tile to smem overlay, then fused LSTM pointwise
    float* Cs = (float*)smp;                   // 128 x 128 fp32 overlay (stage 0)
#pragma unroll
    for (int mt = 0; mt < 2; mt++) {
        int r0 = warpRow + mt * 16 + (lane >> 2);
#pragma unroll
        for (int n8 = 0; n8 < 4; n8++) {
            int col = warpCol + n8 * 8 + 2 * (lane & 3);
            float* c = acc[mt][n8];
            *(float2*)&Cs[r0 * 128 + col]       = make_float2(c[0], c[1]);
            *(float2*)&Cs[(r0 + 8) * 128 + col] = make_float2(c[2], c[3]);
        }
    }
    __syncthreads();
    __nv_bfloat16* X2h_w = g_X2h[par ^ 1];
    __nv_bfloat16* X2l_w = g_X2l[par ^ 1];
#pragma unroll
    for (int it = 0; it < 8; it++) {
        int cell = tid + 512 * it;
        int row = cell >> 5, jq = cell & 31;
        int grow = rowBase + row;
        int j = by * 32 + jq;
        float4 gt = *(const float4*)&Cs[row * 128 + jq * 4];   // i,f,g,o
        size_t idx = (size_t)grow * HID + j;
        float ig = gt.x + g_bias[j];
        float fg = gt.y + g_bias[HID + j];
        float gg = gt.z + g_bias[2 * HID + j];
        float og = gt.w + g_bias[3 * HID + j];
        float cn = sigf(fg) * g_c[idx] + sigf(ig) * tanhf(gg);
        g_c[idx] = cn;
        float hv = sigf(og) * tanhf(cn);
        hout[idx] = hv;
        // write split(h) into the OTHER buffer's h-half for next step
        __nv_bfloat16 hb = __float2bfloat16(hv);
        X2h_w[(size_t)grow * 256 + 128 + j] = hb;
        X2l_w[(size_t)grow * 256 + 128 + j] = __float2bfloat16(hv - __bfloat162float(hb));
    }
}

// ---------------- output: softmax(h @ W_out^T) ----------------
__global__ void out_kernel(const float* __restrict__ hin,
                           const float* __restrict__ W_out,
                           float* __restrict__ out) {
    int v = (blockIdx.x * blockDim.x + threadIdx.x) >> 5;
    int lane = threadIdx.x & 31;
    if (v >= N_VARS) return;
    float p0 = 0.f, p1 = 0.f, p2 = 0.f;
#pragma unroll
    for (int q = 0; q < 4; q++) {
        int col = lane + q * 32;
        float hv = hin[(size_t)v * HID + col];
        p0 = fmaf(hv, __ldg(&W_out[col]), p0);
        p1 = fmaf(hv, __ldg(&W_out[HID + col]), p1);
        p2 = fmaf(hv, __ldg(&W_out[2 * HID + col]), p2);
    }
#pragma unroll
    for (int o = 16; o > 0; o >>= 1) {
        p0 += __shfl_xor_sync(0xffffffffu, p0, o);
        p1 += __shfl_xor_sync(0xffffffffu, p1, o);
        p2 += __shfl_xor_sync(0xffffffffu, p2, o);
    }
    if (lane == 0) {
        float m = fmaxf(p0, fmaxf(p1, p2));
        float e0 = expf(p0 - m), e1 = expf(p1 - m), e2 = expf(p2 - m);
        float inv = 1.f / (e0 + e1 + e2);
        out[v * 3 + 0] = e0 * inv;
        out[v * 3 + 1] = e1 * inv;
        out[v * 3 + 2] = e2 * inv;
    }
}

// ---------------- launch ----------------
extern "C" void kernel_launch(void* const* d_in, const int* in_sizes, int n_in,
                              void* d_out, int out_size) {
    const float* h0      = (const float*)d_in[0];
    const float* var_reg = (const float*)d_in[1];
    const float* W_msg   = (const float*)d_in[2];
    const float* gamma   = (const float*)d_in[3];
    const float* beta    = (const float*)d_in[4];
    const float* W_ih    = (const float*)d_in[5];
    const float* W_hh    = (const float*)d_in[6];
    const float* b_ih    = (const float*)d_in[7];
    const float* b_hh    = (const float*)d_in[8];
    const float* W_out   = (const float*)d_in[9];
    const int*   ei      = (const int*)d_in[10];
    (void)in_sizes; (void)n_in;

    cudaFuncSetAttribute(rec_mma,   cudaFuncAttributeMaxDynamicSharedMemorySize, SMEMSZ);
    cudaFuncSetAttribute(gates_mma, cudaFuncAttributeMaxDynamicSharedMemorySize, SMEMSZ);

    float *hA, *hB, *cbuf;
    int *degi, *cur;
    cudaGetSymbolAddress((void**)&hA, g_hA);
    cudaGetSymbolAddress((void**)&hB, g_hB);
    cudaGetSymbolAddress((void**)&cbuf, g_c);
    cudaGetSymbolAddress((void**)&degi, g_degi);
    cudaGetSymbolAddress((void**)&cur, g_cur);

    cudaStream_t s = 0;
    cudaMemcpyAsync(hA, h0, (size_t)N_VARS * HID * sizeof(float),
                    cudaMemcpyDeviceToDevice, s);
    cudaMemsetAsync(hA + (size_t)N_VARS * HID, 0,
                    (size_t)(NP - N_VARS) * HID * sizeof(float), s);
    cudaMemsetAsync(cbuf, 0, (size_t)NP * HID * sizeof(float), s);
    cudaMemsetAsync(degi, 0, (size_t)NP * sizeof(int), s);
    cudaMemsetAsync(cur, 0, (size_t)NP * sizeof(int), s);

    prep_kernel<<<512, 256, 0, s>>>(W_msg, W_ih, W_hh, b_ih, b_hh);
    degcnt_kernel<<<(2 * N_EDGES + 255) / 256, 256, 0, s>>>(ei);
    scan_kernel<<<1, 1024, 0, s>>>();
    fill_kernel<<<(2 * N_EDGES + 255) / 256, 256, 0, s>>>(ei);
    h0split<<<(NP * 16 + 255) / 256, 256, 0, s>>>(hA);

    const float* hin = hA;
    float* hout = hB;
    for (int st = 0; st < STEPS; ++st) {
        int par = st & 1;
        gather_kernel<<<(N_VARS * 32 + 255) / 256, 256, 0, s>>>(hin);
        rec_mma<<<NBLK, 512, SMEMSZ, s>>>(var_reg);
        bn_finalize<<<1, HID, 0, s>>>(gamma, beta);
        x2_convert<<<(NP * 16 + 255) / 256, 256, 0, s>>>(par);
        gates_mma<<<dim3(NBLK, 4), 512, SMEMSZ, s>>>(hout, par);
        const float* tmp = hout;
        hout = (float*)hin;
        hin = tmp;
    }
    out_kernel<<<(N_VARS * 32 + 255) / 256, 256, 0, s>>>(hin, W_out, (float*)d_out);
}